// round 1
// baseline (speedup 1.0000x reference)
#include <cuda_runtime.h>
#include <math.h>

#define NP 8732
#define NG 20
#define NC 21
#define NB 128
#define THREADS 512
#define NWARP (THREADS/32)

struct Smem {
  float iou[NP];                 // per-prior best IoU (overridden to 2.0 at forced matches)
  unsigned lc[NP];               // loss_c bit patterns (0 for positives)
  unsigned long long bestp[NG];  // packed (iou_bits<<32)|~p per GT
  float gx0[NG], gy0[NG], gx1[NG], gy1[NG], ga[NG];
  int glab[NG];
  unsigned char bidx[NP];        // per-prior best GT index (0..19)
  float redf[NWARP];
  int   redi[NWARP];
  float s_bf; int s_bi;
};

__device__ float g_loc_acc;
__device__ float g_conf_acc;
__device__ int   g_npos_acc;

__global__ void ssd_zero_kernel() {
  g_loc_acc = 0.f; g_conf_acc = 0.f; g_npos_acc = 0;
}

__device__ __forceinline__ float warpSumF(float v) {
  #pragma unroll
  for (int o = 16; o > 0; o >>= 1) v += __shfl_down_sync(0xffffffffu, v, o);
  return v;
}
__device__ __forceinline__ int warpSumI(int v) {
  #pragma unroll
  for (int o = 16; o > 0; o >>= 1) v += __shfl_down_sync(0xffffffffu, v, o);
  return v;
}

// Block-wide sum with broadcast of the result to all threads.
__device__ __forceinline__ int blockSumI(Smem* s, int v) {
  int tid = threadIdx.x;
  v = warpSumI(v);
  if ((tid & 31) == 0) s->redi[tid >> 5] = v;
  __syncthreads();
  if (tid == 0) {
    int t = 0;
    #pragma unroll
    for (int w = 0; w < NWARP; w++) t += s->redi[w];
    s->s_bi = t;
  }
  __syncthreads();
  return s->s_bi;
}
__device__ __forceinline__ float blockSumF(Smem* s, float v) {
  int tid = threadIdx.x;
  v = warpSumF(v);
  if ((tid & 31) == 0) s->redf[tid >> 5] = v;
  __syncthreads();
  if (tid == 0) {
    float t = 0.f;
    #pragma unroll
    for (int w = 0; w < NWARP; w++) t += s->redf[w];
    s->s_bf = t;
  }
  __syncthreads();
  return s->s_bf;
}

__device__ __forceinline__ float sl1(float x) {
  float a = fabsf(x);
  return a < 1.f ? 0.5f * x * x : a - 0.5f;
}

__global__ void __launch_bounds__(THREADS, 1)
ssd_main_kernel(const float* __restrict__ loc, const float* __restrict__ conf,
                const float* __restrict__ dbox, const float* __restrict__ gtb,
                const int* __restrict__ gtl)
{
  extern __shared__ unsigned char smem_raw[];
  Smem* s = (Smem*)smem_raw;
  const int b = blockIdx.x;
  const int tid = threadIdx.x;

  // ---- Load GT boxes (already corner format), labels, areas into smem ----
  if (tid < NG) {
    float4 g = ((const float4*)gtb)[b * NG + tid];
    s->gx0[tid] = g.x; s->gy0[tid] = g.y; s->gx1[tid] = g.z; s->gy1[tid] = g.w;
    s->ga[tid]  = (g.z - g.x) * (g.w - g.y);
    s->glab[tid] = gtl[b * NG + tid];
    s->bestp[tid] = 0ull;
  }
  __syncthreads();

  // ---- Phase A: IoU matching ----
  unsigned long long lb[NG];
  #pragma unroll
  for (int j = 0; j < NG; j++) lb[j] = 0ull;

  for (int p = tid; p < NP; p += THREADS) {
    float4 d = ((const float4*)dbox)[p];   // cx, cy, w, h
    float hx = 0.5f * d.z, hy = 0.5f * d.w;
    float ax0 = d.x - hx, ay0 = d.y - hy, ax1 = d.x + hx, ay1 = d.y + hy;
    float areaA = d.z * d.w;
    float best = -1.f; int bi = 0;
    #pragma unroll
    for (int j = 0; j < NG; j++) {
      float w = fminf(ax1, s->gx1[j]) - fmaxf(ax0, s->gx0[j]);
      float h = fminf(ay1, s->gy1[j]) - fmaxf(ay0, s->gy0[j]);
      w = fmaxf(w, 0.f); h = fmaxf(h, 0.f);
      float inter = w * h;
      float iou = inter / (areaA + s->ga[j] - inter);
      if (iou > best) { best = iou; bi = j; }   // strict >: keeps FIRST max (JAX argmax axis=1)
      // packed per-GT argmax over priors; ~p so smaller p wins ties (JAX argmax axis=0)
      unsigned long long pk =
          ((unsigned long long)__float_as_uint(iou) << 32) |
          (unsigned)(0xFFFFFFFFu - (unsigned)p);
      lb[j] = lb[j] > pk ? lb[j] : pk;
    }
    s->iou[p] = best;
    s->bidx[p] = (unsigned char)bi;
  }
  #pragma unroll
  for (int j = 0; j < NG; j++) atomicMax(&s->bestp[j], lb[j]);
  __syncthreads();

  // Forced matches: sequential so duplicate best-priors resolve last-write-wins.
  if (tid == 0) {
    #pragma unroll
    for (int j = 0; j < NG; j++) {
      unsigned p = 0xFFFFFFFFu - (unsigned)(s->bestp[j] & 0xFFFFFFFFull);
      s->iou[p] = 2.f;
      s->bidx[p] = (unsigned char)j;
    }
  }
  __syncthreads();

  // ---- Phase B: losses (single streaming pass over conf) ----
  float th_loc = 0.f, th_pce = 0.f; int th_np = 0;
  for (int p = tid; p < NP; p += THREADS) {
    float biou = s->iou[p];
    int j = s->bidx[p];
    int lab = (biou > 0.5f) ? s->glab[j] : 0;
    bool pos = lab > 0;

    const float* cp = conf + ((long)b * NP + p) * NC;
    float se = 0.f, cl = 0.f;
    #pragma unroll
    for (int k = 0; k < NC; k++) {
      float v = __ldg(cp + k);
      se += __expf(v);
      if (k == lab) cl = v;
    }
    float ce = __logf(se) - cl;   // lse - conf[label] ; always > 0

    if (pos) {
      float4 d = ((const float4*)dbox)[p];
      float bx0 = s->gx0[j], by0 = s->gy0[j], bx1 = s->gx1[j], by1 = s->gy1[j];
      float e0 = ((bx0 + bx1) * 0.5f - d.x) / (0.1f * d.z);
      float e1 = ((by0 + by1) * 0.5f - d.y) / (0.1f * d.w);
      float e2 = __logf((bx1 - bx0) / d.z) * 5.f;   // /VAR_SIZE(0.2)
      float e3 = __logf((by1 - by0) / d.w) * 5.f;
      float4 L = ((const float4*)loc)[(long)b * NP + p];
      th_loc += sl1(L.x - e0) + sl1(L.y - e1) + sl1(L.z - e2) + sl1(L.w - e3);
      th_pce += ce;
      th_np++;
      s->lc[p] = 0u;
    } else {
      s->lc[p] = __float_as_uint(ce);   // ce >= 0 -> uint bits are order-preserving
    }
  }

  int npos   = blockSumI(s, th_np);
  float locl = blockSumF(s, th_loc);
  float pce  = blockSumF(s, th_pce);
  int k = min(3 * npos, NP - npos);

  // ---- Phase C: sum of top-k loss_c via binary search on bit patterns ----
  // conf_loss = pce + sum(top-k loss_c). Tie handling is value-invariant:
  // top-k sum = sum_{v>t} v + (k - count_{v>t}) * t, t = k-th largest value.
  float topk = 0.f;
  if (k > 0) {
    unsigned lo = 0u, hi = 0x7F800000u;   // c(inf)=0<k holds as upper invariant
    while (lo < hi) {
      unsigned mid = (lo + hi) >> 1;
      int c = 0;
      for (int p = tid; p < NP; p += THREADS) c += (s->lc[p] > mid);
      c = blockSumI(s, c);
      if (c < k) hi = mid; else lo = mid + 1u;
    }
    // lo = bit pattern of the k-th largest value (guaranteed present in set)
    float t = __uint_as_float(lo);
    int m = 0; float sg = 0.f;
    for (int p = tid; p < NP; p += THREADS) {
      unsigned u = s->lc[p];
      if (u > lo) { m++; sg += __uint_as_float(u); }
    }
    m  = blockSumI(s, m);
    sg = blockSumF(s, sg);
    topk = sg + (float)(k - m) * t;
  }

  if (tid == 0) {
    atomicAdd(&g_loc_acc, locl);
    atomicAdd(&g_conf_acc, pce + topk);
    atomicAdd(&g_npos_acc, npos);
  }
}

__global__ void ssd_final_kernel(float* out) {
  float n = (float)max(g_npos_acc, 1);
  out[0] = (g_loc_acc + g_conf_acc) / n;
}

extern "C" void kernel_launch(void* const* d_in, const int* in_sizes, int n_in,
                              void* d_out, int out_size) {
  const float* loc  = (const float*)d_in[0];
  const float* conf = (const float*)d_in[1];
  const float* dbox = (const float*)d_in[2];
  const float* gtb  = (const float*)d_in[3];
  const int*   gtl  = (const int*)d_in[4];
  float* out = (float*)d_out;

  const size_t smem_bytes = sizeof(Smem);
  cudaFuncSetAttribute(ssd_main_kernel,
                       cudaFuncAttributeMaxDynamicSharedMemorySize,
                       (int)smem_bytes);

  ssd_zero_kernel<<<1, 1>>>();
  ssd_main_kernel<<<NB, THREADS, smem_bytes>>>(loc, conf, dbox, gtb, gtl);
  ssd_final_kernel<<<1, 1>>>(out);
}

// round 3
// speedup vs baseline: 1.0005x; 1.0005x over previous
#include <cuda_runtime.h>
#include <math.h>

#define NP 8732
#define NG 20
#define NC 21
#define NB 128
#define THREADS 512
#define NWARP (THREADS/32)

struct Smem {
  float iou[NP];                 // per-prior best IoU (overridden to 2.0 at forced matches)
  unsigned lc[NP];               // loss_c bit patterns (0 for positives)
  unsigned long long bestp[NG];  // packed (iou_bits<<32)|~p per GT
  float gx0[NG], gy0[NG], gx1[NG], gy1[NG], ga[NG];
  int glab[NG];
  unsigned char bidx[NP];        // per-prior best GT index (0..19)
  float redf[NWARP];
  int   redi[NWARP];
  float s_bf; int s_bi;
};

__device__ float g_loc_acc;
__device__ float g_conf_acc;
__device__ int   g_npos_acc;

__global__ void ssd_zero_kernel() {
  g_loc_acc = 0.f; g_conf_acc = 0.f; g_npos_acc = 0;
}

__device__ __forceinline__ float warpSumF(float v) {
  #pragma unroll
  for (int o = 16; o > 0; o >>= 1) v += __shfl_down_sync(0xffffffffu, v, o);
  return v;
}
__device__ __forceinline__ int warpSumI(int v) {
  #pragma unroll
  for (int o = 16; o > 0; o >>= 1) v += __shfl_down_sync(0xffffffffu, v, o);
  return v;
}

// Block-wide sum with broadcast of the result to all threads.
__device__ __forceinline__ int blockSumI(Smem* s, int v) {
  int tid = threadIdx.x;
  v = warpSumI(v);
  if ((tid & 31) == 0) s->redi[tid >> 5] = v;
  __syncthreads();
  if (tid == 0) {
    int t = 0;
    #pragma unroll
    for (int w = 0; w < NWARP; w++) t += s->redi[w];
    s->s_bi = t;
  }
  __syncthreads();
  return s->s_bi;
}
__device__ __forceinline__ float blockSumF(Smem* s, float v) {
  int tid = threadIdx.x;
  v = warpSumF(v);
  if ((tid & 31) == 0) s->redf[tid >> 5] = v;
  __syncthreads();
  if (tid == 0) {
    float t = 0.f;
    #pragma unroll
    for (int w = 0; w < NWARP; w++) t += s->redf[w];
    s->s_bf = t;
  }
  __syncthreads();
  return s->s_bf;
}

__device__ __forceinline__ float sl1(float x) {
  float a = fabsf(x);
  return a < 1.f ? 0.5f * x * x : a - 0.5f;
}

__global__ void __launch_bounds__(THREADS, 1)
ssd_main_kernel(const float* __restrict__ loc, const float* __restrict__ conf,
                const float* __restrict__ dbox, const float* __restrict__ gtb,
                const int* __restrict__ gtl)
{
  extern __shared__ unsigned char smem_raw[];
  Smem* s = (Smem*)smem_raw;
  const int b = blockIdx.x;
  const int tid = threadIdx.x;

  // ---- Load GT boxes (already corner format), labels, areas into smem ----
  if (tid < NG) {
    float4 g = ((const float4*)gtb)[b * NG + tid];
    s->gx0[tid] = g.x; s->gy0[tid] = g.y; s->gx1[tid] = g.z; s->gy1[tid] = g.w;
    s->ga[tid]  = (g.z - g.x) * (g.w - g.y);
    s->glab[tid] = gtl[b * NG + tid];
    s->bestp[tid] = 0ull;
  }
  __syncthreads();

  // ---- Phase A: IoU matching ----
  unsigned long long lb[NG];
  #pragma unroll
  for (int j = 0; j < NG; j++) lb[j] = 0ull;

  for (int p = tid; p < NP; p += THREADS) {
    float4 d = ((const float4*)dbox)[p];   // cx, cy, w, h
    float hx = 0.5f * d.z, hy = 0.5f * d.w;
    float ax0 = d.x - hx, ay0 = d.y - hy, ax1 = d.x + hx, ay1 = d.y + hy;
    float areaA = d.z * d.w;
    float best = -1.f; int bi = 0;
    #pragma unroll
    for (int j = 0; j < NG; j++) {
      float w = fminf(ax1, s->gx1[j]) - fmaxf(ax0, s->gx0[j]);
      float h = fminf(ay1, s->gy1[j]) - fmaxf(ay0, s->gy0[j]);
      w = fmaxf(w, 0.f); h = fmaxf(h, 0.f);
      float inter = w * h;
      float iou = inter / (areaA + s->ga[j] - inter);
      if (iou > best) { best = iou; bi = j; }   // strict >: keeps FIRST max (JAX argmax axis=1)
      // packed per-GT argmax over priors; ~p so smaller p wins ties (JAX argmax axis=0)
      unsigned long long pk =
          ((unsigned long long)__float_as_uint(iou) << 32) |
          (unsigned)(0xFFFFFFFFu - (unsigned)p);
      lb[j] = lb[j] > pk ? lb[j] : pk;
    }
    s->iou[p] = best;
    s->bidx[p] = (unsigned char)bi;
  }
  #pragma unroll
  for (int j = 0; j < NG; j++) atomicMax(&s->bestp[j], lb[j]);
  __syncthreads();

  // Forced matches: sequential so duplicate best-priors resolve last-write-wins.
  if (tid == 0) {
    #pragma unroll
    for (int j = 0; j < NG; j++) {
      unsigned p = 0xFFFFFFFFu - (unsigned)(s->bestp[j] & 0xFFFFFFFFull);
      s->iou[p] = 2.f;
      s->bidx[p] = (unsigned char)j;
    }
  }
  __syncthreads();

  // ---- Phase B: losses (single streaming pass over conf) ----
  float th_loc = 0.f, th_pce = 0.f; int th_np = 0;
  for (int p = tid; p < NP; p += THREADS) {
    float biou = s->iou[p];
    int j = s->bidx[p];
    int lab = (biou > 0.5f) ? s->glab[j] : 0;
    bool pos = lab > 0;

    const float* cp = conf + ((long)b * NP + p) * NC;
    float se = 0.f, cl = 0.f;
    #pragma unroll
    for (int k = 0; k < NC; k++) {
      float v = __ldg(cp + k);
      se += __expf(v);
      if (k == lab) cl = v;
    }
    float ce = __logf(se) - cl;   // lse - conf[label] ; always > 0

    if (pos) {
      float4 d = ((const float4*)dbox)[p];
      float bx0 = s->gx0[j], by0 = s->gy0[j], bx1 = s->gx1[j], by1 = s->gy1[j];
      float e0 = ((bx0 + bx1) * 0.5f - d.x) / (0.1f * d.z);
      float e1 = ((by0 + by1) * 0.5f - d.y) / (0.1f * d.w);
      float e2 = __logf((bx1 - bx0) / d.z) * 5.f;   // /VAR_SIZE(0.2)
      float e3 = __logf((by1 - by0) / d.w) * 5.f;
      float4 L = ((const float4*)loc)[(long)b * NP + p];
      th_loc += sl1(L.x - e0) + sl1(L.y - e1) + sl1(L.z - e2) + sl1(L.w - e3);
      th_pce += ce;
      th_np++;
      s->lc[p] = 0u;
    } else {
      s->lc[p] = __float_as_uint(ce);   // ce >= 0 -> uint bits are order-preserving
    }
  }

  int npos   = blockSumI(s, th_np);
  float locl = blockSumF(s, th_loc);
  float pce  = blockSumF(s, th_pce);
  int k = min(3 * npos, NP - npos);

  // ---- Phase C: sum of top-k loss_c via binary search on bit patterns ----
  // conf_loss = pce + sum(top-k loss_c). Tie handling is value-invariant:
  // top-k sum = sum_{v>t} v + (k - count_{v>t}) * t, t = k-th largest value.
  float topk = 0.f;
  if (k > 0) {
    unsigned lo = 0u, hi = 0x7F800000u;   // c(inf)=0<k holds as upper invariant
    while (lo < hi) {
      unsigned mid = (lo + hi) >> 1;
      int c = 0;
      for (int p = tid; p < NP; p += THREADS) c += (s->lc[p] > mid);
      c = blockSumI(s, c);
      if (c < k) hi = mid; else lo = mid + 1u;
    }
    // lo = bit pattern of the k-th largest value (guaranteed present in set)
    float t = __uint_as_float(lo);
    int m = 0; float sg = 0.f;
    for (int p = tid; p < NP; p += THREADS) {
      unsigned u = s->lc[p];
      if (u > lo) { m++; sg += __uint_as_float(u); }
    }
    m  = blockSumI(s, m);
    sg = blockSumF(s, sg);
    topk = sg + (float)(k - m) * t;
  }

  if (tid == 0) {
    atomicAdd(&g_loc_acc, locl);
    atomicAdd(&g_conf_acc, pce + topk);
    atomicAdd(&g_npos_acc, npos);
  }
}

__global__ void ssd_final_kernel(float* out) {
  float n = (float)max(g_npos_acc, 1);
  out[0] = (g_loc_acc + g_conf_acc) / n;
}

extern "C" void kernel_launch(void* const* d_in, const int* in_sizes, int n_in,
                              void* d_out, int out_size) {
  const float* loc  = (const float*)d_in[0];
  const float* conf = (const float*)d_in[1];
  const float* dbox = (const float*)d_in[2];
  const float* gtb  = (const float*)d_in[3];
  const int*   gtl  = (const int*)d_in[4];
  float* out = (float*)d_out;

  const size_t smem_bytes = sizeof(Smem);
  cudaFuncSetAttribute(ssd_main_kernel,
                       cudaFuncAttributeMaxDynamicSharedMemorySize,
                       (int)smem_bytes);

  ssd_zero_kernel<<<1, 1>>>();
  ssd_main_kernel<<<NB, THREADS, smem_bytes>>>(loc, conf, dbox, gtb, gtl);
  ssd_final_kernel<<<1, 1>>>(out);
}

// round 4
// speedup vs baseline: 1.1430x; 1.1425x over previous
#include <cuda_runtime.h>
#include <math.h>

#define NP 8732
#define NG 20
#define NC 21
#define NB 128
#define TPB 512
#define NWARP (TPB/32)
#define PER 18            // ceil(NP/TPB)
#define TILE 512
#define NTILE 18          // 17 full tiles + one of 28 priors (both cnt%4==0)

__device__ float g_ce0[(size_t)NB * NP];   // lse - conf[...,0] per (b,p)
__device__ float g_loc_acc, g_conf_acc;
__device__ int   g_npos_acc, g_done;

__device__ __forceinline__ float warpSumF(float v) {
  #pragma unroll
  for (int o = 16; o > 0; o >>= 1) v += __shfl_down_sync(0xffffffffu, v, o);
  return v;
}
__device__ __forceinline__ int warpSumI(int v) {
  #pragma unroll
  for (int o = 16; o > 0; o >>= 1) v += __shfl_down_sync(0xffffffffu, v, o);
  return v;
}
__device__ __forceinline__ float sl1(float x) {
  float a = fabsf(x);
  return a < 1.f ? 0.5f * x * x : a - 0.5f;
}

// ================= Kernel 1: per-(b,p) logsumexp-based ce0 =================
// ce0[b,p] = log(sum_k exp(conf[b,p,k])) - conf[b,p,0]  (> 0 always)
__global__ void __launch_bounds__(TPB)
lse_kernel(const float* __restrict__ conf) {
  __shared__ float tile[TILE * NC];   // 43008 B
  const int t = blockIdx.x;
  const int b = blockIdx.y;
  if (t == 0 && b == 0 && threadIdx.x == 0) {
    g_loc_acc = 0.f; g_conf_acc = 0.f; g_npos_acc = 0; g_done = 0;
  }
  const int p0  = t * TILE;
  const int cnt = min(TILE, NP - p0);
  const int nf4 = cnt * NC / 4;       // cnt in {512,28} -> cnt*21 % 4 == 0
  const float4* src = (const float4*)(conf + ((size_t)b * NP + p0) * NC);
  float4* dst = (float4*)tile;
  for (int i = threadIdx.x; i < nf4; i += TPB) dst[i] = src[i];
  __syncthreads();
  const int x = threadIdx.x;
  if (x < cnt) {
    const float* row = tile + x * NC;   // stride 21: bank-conflict-free
    float s0 = 0.f, s1 = 0.f, s2 = 0.f;
    #pragma unroll
    for (int k = 0; k < 21; k += 3) {
      s0 += __expf(row[k]);
      s1 += __expf(row[k + 1]);
      s2 += __expf(row[k + 2]);
    }
    float lse = __logf(s0 + s1 + s2);
    g_ce0[(size_t)b * NP + p0 + x] = lse - row[0];
  }
}

// ================= Kernel 2: per-batch match + loss + top-k =================
struct Smem3 {
  float iou[NP];
  unsigned char bidx[NP];
  float4 g4[NG];
  float ga[NG];
  int glab[NG];
  unsigned long long bestp[NG];
  int   redi[2][NWARP];
  float redf[3][NWARP];
};

__global__ void __launch_bounds__(TPB, 1)
match_kernel(const float* __restrict__ loc, const float* __restrict__ conf,
             const float* __restrict__ dbox, const float* __restrict__ gtb,
             const int* __restrict__ gtl, float* __restrict__ out)
{
  __shared__ Smem3 s;   // ~44.6 KB static
  const int b   = blockIdx.x;
  const int tid = threadIdx.x;
  const int wi  = tid >> 5, li = tid & 31;

  if (tid < NG) {
    float4 g = ((const float4*)gtb)[b * NG + tid];
    s.g4[tid]   = g;
    s.ga[tid]   = (g.z - g.x) * (g.w - g.y);
    s.glab[tid] = gtl[b * NG + tid];
    s.bestp[tid] = 0ull;
  }
  __syncthreads();

  // ---- Phase A: IoU matching ----
  unsigned long long lb[NG];
  #pragma unroll
  for (int j = 0; j < NG; j++) lb[j] = 0ull;

  #pragma unroll
  for (int i = 0; i < PER; i++) {
    int p = tid + i * TPB;
    if (p < NP) {
      float4 d = ((const float4*)dbox)[p];        // cx,cy,w,h
      float hx = 0.5f * d.z, hy = 0.5f * d.w;
      float ax0 = d.x - hx, ay0 = d.y - hy, ax1 = d.x + hx, ay1 = d.y + hy;
      float areaA = d.z * d.w;
      float best = -1.f; int bi = 0;
      #pragma unroll
      for (int j = 0; j < NG; j++) {
        float4 g = s.g4[j];
        float w = fminf(ax1, g.z) - fmaxf(ax0, g.x);
        float h = fminf(ay1, g.w) - fmaxf(ay0, g.y);
        w = fmaxf(w, 0.f); h = fmaxf(h, 0.f);
        float inter = w * h;
        float iou = __fdividef(inter, areaA + s.ga[j] - inter);
        if (iou > best) { best = iou; bi = j; }   // strict >: FIRST max (argmax axis=1)
        // per-GT argmax over priors; ~p so smaller p wins ties (argmax axis=0)
        unsigned long long pk =
            ((unsigned long long)__float_as_uint(iou) << 32) |
            (unsigned)(0xFFFFFFFFu - (unsigned)p);
        lb[j] = lb[j] > pk ? lb[j] : pk;
      }
      s.iou[p]  = best;
      s.bidx[p] = (unsigned char)bi;
    }
  }
  // warp-reduce packed maxima, then one single-lane smem atomic per (warp,GT)
  #pragma unroll
  for (int j = 0; j < NG; j++) {
    unsigned long long v = lb[j];
    #pragma unroll
    for (int o = 16; o > 0; o >>= 1) {
      unsigned long long u = __shfl_down_sync(0xffffffffu, v, o);
      v = v > u ? v : u;
    }
    if (li == 0) atomicMax(&s.bestp[j], v);
  }
  __syncthreads();

  // Forced matches: sequential last-write-wins for duplicate best priors.
  if (tid == 0) {
    #pragma unroll
    for (int j = 0; j < NG; j++) {
      unsigned p = 0xFFFFFFFFu - (unsigned)(s.bestp[j] & 0xFFFFFFFFull);
      s.iou[p]  = 2.f;
      s.bidx[p] = (unsigned char)j;
    }
  }
  __syncthreads();

  // ---- Phase B: losses; lc kept in registers ----
  float th_loc = 0.f, th_pce = 0.f; int th_np = 0;
  unsigned lcr[PER];
  #pragma unroll
  for (int i = 0; i < PER; i++) {
    int p = tid + i * TPB;
    unsigned v = 0u;
    if (p < NP) {
      float biou = s.iou[p];
      int j = s.bidx[p];
      float ce0 = g_ce0[(size_t)b * NP + p];      // coalesced, L2-hot
      if (biou > 0.5f) {                          // pos (gt labels are all >=1)
        int lab = s.glab[j];
        const float* cp = conf + ((size_t)b * NP + p) * NC;
        float c0 = __ldg(cp), cl = __ldg(cp + lab);
        th_pce += ce0 + c0 - cl;                  // ce = lse - conf[lab]
        th_np++;
        float4 d = ((const float4*)dbox)[p];
        float4 g = s.g4[j];
        float e0 = ((g.x + g.z) * 0.5f - d.x) / (0.1f * d.z);
        float e1 = ((g.y + g.w) * 0.5f - d.y) / (0.1f * d.w);
        float e2 = __logf((g.z - g.x) / d.z) * 5.f;
        float e3 = __logf((g.w - g.y) / d.w) * 5.f;
        float4 L = ((const float4*)loc)[(size_t)b * NP + p];
        th_loc += sl1(L.x - e0) + sl1(L.y - e1) + sl1(L.z - e2) + sl1(L.w - e3);
      } else {
        v = __float_as_uint(ce0);                 // ce0 > 0: bits order-preserving
      }
    }
    lcr[i] = v;
  }

  // Fused block reduction (np, loc, pce) with broadcast via smem partials
  {
    float a = warpSumF(th_loc), c = warpSumF(th_pce); int n = warpSumI(th_np);
    if (li == 0) { s.redf[0][wi] = a; s.redf[1][wi] = c; s.redi[0][wi] = n; }
  }
  __syncthreads();
  float locl = 0.f, pce = 0.f; int npos = 0;
  #pragma unroll
  for (int w = 0; w < NWARP; w++) {
    locl += s.redf[0][w]; pce += s.redf[1][w]; npos += s.redi[0][w];
  }
  int k = min(3 * npos, NP - npos);

  // ---- Phase C: top-k sum via binary search on bit patterns ----
  float topk = 0.f;
  int par = 1;                       // double-buffered partials: 1 barrier/step
  if (k > 0) {
    unsigned lo = 0u, hi = 0x7F800000u;
    while (lo < hi) {
      unsigned mid = (lo + hi) >> 1;
      int c = 0;
      #pragma unroll
      for (int i = 0; i < PER; i++) c += (lcr[i] > mid);
      c = warpSumI(c);
      if (li == 0) s.redi[par][wi] = c;
      __syncthreads();
      int tot = 0;
      #pragma unroll
      for (int w = 0; w < NWARP; w++) tot += s.redi[par][w];
      if (tot < k) hi = mid; else lo = mid + 1u;   // uniform across block
      par ^= 1;
    }
    // lo = bit pattern of k-th largest; topk = sum_{v>t} v + (k - m) * t
    int m = 0; float sg = 0.f;
    #pragma unroll
    for (int i = 0; i < PER; i++) {
      unsigned u = lcr[i];
      if (u > lo) { m++; sg += __uint_as_float(u); }
    }
    m = warpSumI(m); sg = warpSumF(sg);
    if (li == 0) { s.redi[par][wi] = m; s.redf[2][wi] = sg; }
    __syncthreads();
    int mt = 0; float sgt = 0.f;
    #pragma unroll
    for (int w = 0; w < NWARP; w++) { mt += s.redi[par][w]; sgt += s.redf[2][w]; }
    topk = sgt + (float)(k - mt) * __uint_as_float(lo);
  }

  if (tid == 0) {
    atomicAdd(&g_loc_acc, locl);
    atomicAdd(&g_conf_acc, pce + topk);
    atomicAdd(&g_npos_acc, npos);
    __threadfence();
    int tk = atomicAdd(&g_done, 1);
    if (tk == NB - 1) {              // last block finalizes
      float L = atomicAdd(&g_loc_acc, 0.f);
      float C = atomicAdd(&g_conf_acc, 0.f);
      int  Nn = atomicAdd(&g_npos_acc, 0);
      out[0] = (L + C) / (float)max(Nn, 1);
    }
  }
}

extern "C" void kernel_launch(void* const* d_in, const int* in_sizes, int n_in,
                              void* d_out, int out_size) {
  const float* loc  = (const float*)d_in[0];
  const float* conf = (const float*)d_in[1];
  const float* dbox = (const float*)d_in[2];
  const float* gtb  = (const float*)d_in[3];
  const int*   gtl  = (const int*)d_in[4];
  float* out = (float*)d_out;

  lse_kernel<<<dim3(NTILE, NB), TPB>>>(conf);
  match_kernel<<<NB, TPB>>>(loc, conf, dbox, gtb, gtl, out);
}